// round 8
// baseline (speedup 1.0000x reference)
#include <cuda_runtime.h>
#include <cstdint>

// Problem constants (from reference)
#define SIGMA_INV 1.0e4f   // 1/SIGMA
#define GAMMA_INV 1.0e4f   // 1/GAMMA
#define ZFARV 100.0f
#define ZNEARV 1.0f
#define EPSV 1e-10f
#define MAX_F 100000
#define MAX_V 50000
#define Q14_SCALE 8191.0f
#define Q14_INV   (1.0f / 8191.0f)

// Packed per-face record, 16 bytes: components c0..c7 as 14-bit snorm at bit
// 14*i, c8 as 16-bit slot at bit 112 (quantized with scale 8191).
// Component order: n0x n0y n0z n1x n1y n1z n2x n2y n2z  ->  c0..c8
__device__ uint4  g_facen[MAX_F];
__device__ float4 g_vn4[MAX_V];   // vertex normals padded to 16B

__device__ __forceinline__ unsigned long long q14(float a) {
    int ia = __float2int_rn(a * Q14_SCALE);
    return (unsigned long long)((unsigned)ia & 0x3FFFu);
}

__global__ void pad_vn_kernel(const float* __restrict__ vn, int V) {
    int v = blockIdx.x * blockDim.x + threadIdx.x;
    if (v >= V) return;
    g_vn4[v] = make_float4(vn[3 * v], vn[3 * v + 1], vn[3 * v + 2], 0.f);
}

__global__ void gather_face_normals_kernel(const int* __restrict__ faces, int F) {
    int f = blockIdx.x * blockDim.x + threadIdx.x;
    if (f >= F) return;
    int v0 = __ldg(&faces[3 * f + 0]);
    int v1 = __ldg(&faces[3 * f + 1]);
    int v2 = __ldg(&faces[3 * f + 2]);
    float4 n0 = __ldg(&g_vn4[v0]);
    float4 n1 = __ldg(&g_vn4[v1]);
    float4 n2 = __ldg(&g_vn4[v2]);

    unsigned long long lo = q14(n0.x) | (q14(n0.y) << 14) | (q14(n0.z) << 28)
                          | (q14(n1.x) << 42) | ((q14(n1.y) & 0xFFull) << 56);
    unsigned long long hi = (q14(n1.y) >> 8) | (q14(n1.z) << 6) | (q14(n2.x) << 20)
                          | (q14(n2.y) << 34)
                          | ((unsigned long long)((unsigned)__float2int_rn(n2.z * Q14_SCALE) & 0xFFFFu) << 48);

    uint4 r;
    r.x = (unsigned)lo;
    r.y = (unsigned)(lo >> 32);
    r.z = (unsigned)hi;
    r.w = (unsigned)(hi >> 32);
    g_facen[f] = r;
}

__device__ __forceinline__ int sext14(unsigned v) {
    return ((int)(v << 18)) >> 18;
}

// 2 threads per pixel (half h = tid parity handles fragments 4h..4h+3).
// Grid-stride loop over half-pixels with prefetch of the next iteration's
// p2f vector, breaking the serial f->gather dependency chain across
// iterations and keeping loads continuously in flight.
__global__ void
shade_blend_kernel(const float4* __restrict__ bary,   // 6 float4 per pixel
                   const float4* __restrict__ zbuf,   // 2 float4 per pixel
                   const float4* __restrict__ dists,  // 2 float4 per pixel
                   const int4*   __restrict__ p2f,    // 2 int4 per pixel
                   float2*       __restrict__ out,    // 2 float2 per pixel
                   int nhalf) {                        // npix*2
    const int stride = gridDim.x * blockDim.x;
    int hp = blockIdx.x * blockDim.x + threadIdx.x;
    if (hp >= nhalf) return;

    // prologue: load first f
    int f[4];
    {
        int pi = hp >> 1, hi2 = hp & 1;
        *reinterpret_cast<int4*>(f) = __ldcs(&p2f[pi * 2 + hi2]);
    }

    for (; hp < nhalf; hp += stride) {
        const int p = hp >> 1;
        const int h = hp & 1;

        // prefetch next iteration's p2f (clamped; result unused on last iter)
        int hpn = hp + stride;
        int hpc = hpn < nhalf ? hpn : (nhalf - 1);
        int fn[4];
        *reinterpret_cast<int4*>(fn) = __ldcs(&p2f[(hpc >> 1) * 2 + (hpc & 1)]);

        // gathers for current iteration (f already resident from prev iter)
        uint4 r0 = __ldg(&g_facen[f[0] >= 0 ? f[0] : 0]);
        uint4 r1 = __ldg(&g_facen[f[1] >= 0 ? f[1] : 0]);
        uint4 r2 = __ldg(&g_facen[f[2] >= 0 ? f[2] : 0]);
        uint4 r3 = __ldg(&g_facen[f[3] >= 0 ? f[3] : 0]);

        float z[4]; *reinterpret_cast<float4*>(z) = __ldcs(&zbuf[p * 2 + h]);
        float d[4]; *reinterpret_cast<float4*>(d) = __ldcs(&dists[p * 2 + h]);

        float b[12];
        float4* bv = reinterpret_cast<float4*>(b);
#pragma unroll
        for (int i = 0; i < 3; i++) bv[i] = __ldcs(&bary[p * 6 + h * 3 + i]);

        // ---- compute ----
        float zinv[4];
        float zl = EPSV;
#pragma unroll
        for (int k = 0; k < 4; k++) {
            bool m = f[k] >= 0;
            zinv[k] = m ? (ZFARV - z[k]) * (1.0f / (ZFARV - ZNEARV)) : 0.0f;
            zl = fmaxf(zl, zinv[k]);
        }
        float zmax = fmaxf(zl, __shfl_xor_sync(0xffffffffu, zl, 1));

        float ax = 0.f, ay = 0.f, az = 0.f, wsum = 0.f, om = 1.0f;

        const uint4 rr[4] = {r0, r1, r2, r3};
#pragma unroll
        for (int k = 0; k < 4; k++) {
            bool m = f[k] >= 0;
            uint4 r = rr[k];

            float prob = m ? __fdividef(1.0f, 1.0f + __expf(d[k] * SIGMA_INV)) : 0.0f;
            om *= (1.0f - prob);
            float w = prob * __expf((zinv[k] - zmax) * GAMMA_INV);
            wsum += w;

            float s = w * Q14_INV;           // fold weight + dequant scale
            float w0 = b[3 * k + 0] * s;
            float w1 = b[3 * k + 1] * s;
            float w2 = b[3 * k + 2] * s;

            int c0 = sext14(r.x);
            int c1 = ((int)(r.x << 4)) >> 18;
            int c2 = sext14(__funnelshift_r(r.x, r.y, 28));
            int c3 = ((int)(r.y << 8)) >> 18;
            int c4 = sext14(__funnelshift_r(r.y, r.z, 24));
            int c5 = ((int)(r.z << 12)) >> 18;
            int c6 = sext14(__funnelshift_r(r.z, r.w, 20));
            int c7 = ((int)(r.w << 16)) >> 18;
            int c8 = ((int)r.w) >> 16;

            ax += w0 * (float)c0 + w1 * (float)c3 + w2 * (float)c6;
            ay += w0 * (float)c1 + w1 * (float)c4 + w2 * (float)c7;
            az += w0 * (float)c2 + w1 * (float)c5 + w2 * (float)c8;
        }

        // combine the two half-pixel partials (both threads end with full sums)
        ax   += __shfl_xor_sync(0xffffffffu, ax,   1);
        ay   += __shfl_xor_sync(0xffffffffu, ay,   1);
        az   += __shfl_xor_sync(0xffffffffu, az,   1);
        wsum += __shfl_xor_sync(0xffffffffu, wsum, 1);
        om   *= __shfl_xor_sync(0xffffffffu, om,   1);

        float delta = __expf((EPSV - zmax) * GAMMA_INV);
        wsum += delta;
        float inv = __fdividef(1.0f, wsum);

        // paired 8B stores: h==0 writes (r,g), h==1 writes (b,a) -> fully
        // coalesced 512B per warp
        float2 o = (h == 0)
            ? make_float2((ax + delta) * inv, (ay + delta) * inv)
            : make_float2((az + delta) * inv, 1.0f - om);
        __stcs(&out[p * 2 + h], o);

        f[0] = fn[0]; f[1] = fn[1]; f[2] = fn[2]; f[3] = fn[3];
    }
}

extern "C" void kernel_launch(void* const* d_in, const int* in_sizes, int n_in,
                              void* d_out, int out_size) {
    // metadata order: bary_coords, zbuf, dists, verts_normals, pix_to_face, faces
    const float* bary  = (const float*)d_in[0];
    const float* zbuf  = (const float*)d_in[1];
    const float* dists = (const float*)d_in[2];
    const float* vn    = (const float*)d_in[3];
    const int*   p2f   = (const int*)d_in[4];
    const int*   faces = (const int*)d_in[5];

    const int V = in_sizes[3] / 3;
    const int F = in_sizes[5] / 3;
    const int npix = in_sizes[1] / 8;
    const int nhalf = npix * 2;

    pad_vn_kernel<<<(V + 255) / 256, 256>>>(vn, V);
    gather_face_normals_kernel<<<(F + 255) / 256, 256>>>(faces, F);

    {
        int threads = 128;
        int blocks = 2048;   // grid-stride: ~8 half-pixels per thread
        shade_blend_kernel<<<blocks, threads>>>(
            (const float4*)bary, (const float4*)zbuf, (const float4*)dists,
            (const int4*)p2f, (float2*)d_out, nhalf);
    }
}